// round 3
// baseline (speedup 1.0000x reference)
#include <cuda_runtime.h>
#include <cstdint>

// VanillaRNN: p = (scan_t h = tanh(x_t @ Whx + h @ Whh + bh)) @ Wph + bp
// B=256, T=1024, D=64, H=512, C=10, all fp32.
//
// Round 3: persistent kernel, 128 blocks x 512 threads, split-K(4).
//  - Distributed-flag grid barrier (no atomic contention, 1 fence/block).
//  - x_{t+1} staged before the barrier; only h staging is post-barrier.

#define SEQ_LEN   1024
#define IN_DIM    64
#define HID       512
#define NCLS      10
#define BATCH     256
#define KTOT      (IN_DIM + HID)   // 576

#define COL_TILES 8
#define ROW_TILES 16
#define GRID_DIM  (COL_TILES * ROW_TILES)  // 128 blocks, 1 CTA/SM
#define NTHREADS  512
#define KGROUPS   4
#define KCHUNK    (KTOT / KGROUPS)         // 144
#define TILE_C    64
#define TILE_R    16

#define SV_PITCH  18   // float2 per k row (pad: 16B align + bank spread)

// SMEM:
//   sW : [KTOT][TILE_C] float    = 147456 B
//   sV : [KTOT][SV_PITCH] float2 =  82944 B (value duplicated .x/.y)
//        h-region (k>=64) reused as reduction scratch float2[4][512]
//   sB : [TILE_C] float          =    256 B
#define SW_BYTES  (KTOT * TILE_C * 4)
#define SV_BYTES  (KTOT * SV_PITCH * 8)
#define SMEM_BYTES (SW_BYTES + SV_BYTES + TILE_C * 4)   // 230656

__device__ float    g_h[2][BATCH][HID];        // double-buffered hidden state
__device__ unsigned g_flags[GRID_DIM * 32];    // 1 flag / block, 128B stride

__device__ __forceinline__ float2 unpk(unsigned long long v) {
    float2 f;
    asm("mov.b64 {%0, %1}, %2;" : "=f"(f.x), "=f"(f.y) : "l"(v));
    return f;
}
__device__ __forceinline__ void fma2(unsigned long long& d,
                                     unsigned long long a,
                                     unsigned long long b) {
    asm("fma.rn.f32x2 %0, %1, %2, %0;" : "+l"(d) : "l"(a), "l"(b));
}

__global__ void __launch_bounds__(NTHREADS, 1)
rnn_persistent_kernel(const float* __restrict__ x,
                      const float* __restrict__ Whx,
                      const float* __restrict__ Whh,
                      const float* __restrict__ Wph,
                      const float* __restrict__ bh,
                      const float* __restrict__ bp,
                      float* __restrict__ out)
{
    extern __shared__ unsigned char smem[];
    float*  sW   = reinterpret_cast<float*>(smem);               // [KTOT][64]
    float2* sV   = reinterpret_cast<float2*>(smem + SW_BYTES);   // [KTOT][18]
    float2* sRed = sV + IN_DIM * SV_PITCH;                       // in h-region
    float*  sB   = reinterpret_cast<float*>(smem + SW_BYTES + SV_BYTES);

    const int tid = threadIdx.x;
    const int bid = blockIdx.x;
    const int jt  = bid & (COL_TILES - 1);   // col tile
    const int it  = bid >> 3;                // row tile
    const int c0  = jt * TILE_C;
    const int r0  = it * TILE_R;

    // ---- one-time: W slice [Whx; Whh][:, c0:c0+64] + bias ----
    for (int idx = tid; idx < KTOT * TILE_C; idx += NTHREADS) {
        int k = idx / TILE_C;
        int c = idx - k * TILE_C;
        float w = (k < IN_DIM) ? Whx[k * HID + c0 + c]
                               : Whh[(k - IN_DIM) * HID + c0 + c];
        sW[k * TILE_C + c] = w;
    }
    if (tid < TILE_C) sB[tid] = bh[c0 + tid];

    // split-K org: 4 groups x 128 threads; within group 2 rows x 4 cols
    const int kg = tid >> 7;
    const int pg = tid & 127;
    const int r4 = pg & 7;                   // rows 2*r4, 2*r4+1
    const int cq = pg >> 3;                  // cols 4*cq..4*cq+3
    const int k0 = kg * KCHUNK;

    const float*  wp = sW + 4 * cq;
    const float2* vp = sV + 2 * r4;

    // reduction mapping: thread finalizes output pair tid
    const int rcp  = tid & 31;               // colpair 0..31
    const int rrow = tid >> 5;               // row 0..15

    // ---- prologue: h_0 = 0 straight into SMEM; stage x_0 ----
    for (int idx = tid; idx < TILE_R * HID; idx += NTHREADS) {
        int r = idx >> 9;
        int k = idx & 511;
        sV[(IN_DIM + k) * SV_PITCH + r] = make_float2(0.f, 0.f);
    }
    for (int idx = tid; idx < TILE_R * IN_DIM; idx += NTHREADS) {
        int r = idx >> 6;
        int k = idx & 63;
        float v = x[(size_t)(r0 + r) * (SEQ_LEN * IN_DIM) + k];
        sV[k * SV_PITCH + r] = make_float2(v, v);
    }

    for (int t = 0; t < SEQ_LEN; ++t) {
        __syncthreads();   // sV (x_t + h_t) ready

        // ---- partial GEMM over this group's K-chunk ----
        unsigned long long a00 = 0, a01 = 0;
        unsigned long long a10 = 0, a11 = 0;
        #pragma unroll 8
        for (int k = k0; k < k0 + KCHUNK; ++k) {
            longlong2 w = *reinterpret_cast<const longlong2*>(wp + k * TILE_C);
            longlong2 v = *reinterpret_cast<const longlong2*>(vp + k * SV_PITCH);
            fma2(a00, (unsigned long long)v.x, (unsigned long long)w.x);
            fma2(a01, (unsigned long long)v.x, (unsigned long long)w.y);
            fma2(a10, (unsigned long long)v.y, (unsigned long long)w.x);
            fma2(a11, (unsigned long long)v.y, (unsigned long long)w.y);
        }
        __syncthreads();   // all sV reads done; h-region reusable as sRed

        // ---- write partials ----
        {
            float2* rb = sRed + kg * 512;
            rb[(2 * r4)     * 32 + 2 * cq    ] = unpk(a00);
            rb[(2 * r4)     * 32 + 2 * cq + 1] = unpk(a01);
            rb[(2 * r4 + 1) * 32 + 2 * cq    ] = unpk(a10);
            rb[(2 * r4 + 1) * 32 + 2 * cq + 1] = unpk(a11);
        }
        __syncthreads();

        // ---- reduce + bias + tanh + store h_new; stage x_{t+1} ----
        {
            float2 s0 = sRed[tid];
            float2 s1 = sRed[512 + tid];
            float2 s2 = sRed[1024 + tid];
            float2 s3 = sRed[1536 + tid];
            float sx = (s0.x + s1.x) + (s2.x + s3.x) + sB[2 * rcp];
            float sy = (s0.y + s1.y) + (s2.y + s3.y) + sB[2 * rcp + 1];
            float2 o = make_float2(tanhf(sx), tanhf(sy));
            float* hn = &g_h[(t + 1) & 1][0][0];
            *reinterpret_cast<float2*>(hn + (r0 + rrow) * HID + c0 + 2 * rcp) = o;
        }
        if (t + 1 < SEQ_LEN) {
            for (int idx = tid; idx < TILE_R * IN_DIM; idx += NTHREADS) {
                int r = idx >> 6;
                int k = idx & 63;
                float v = x[(size_t)(r0 + r) * (SEQ_LEN * IN_DIM)
                            + (size_t)(t + 1) * IN_DIM + k];
                sV[k * SV_PITCH + r] = make_float2(v, v);
            }
        }

        // ---- distributed-flag grid barrier ----
        __syncthreads();                    // h_new stores issued block-wide
        if (tid == 0) {
            __threadfence();                // make h_new visible gpu-wide
            asm volatile("st.release.gpu.u32 [%0], %1;"
                         :: "l"(g_flags + bid * 32), "r"(t + 1) : "memory");
        }
        if (tid < 32) {
            const unsigned target = (unsigned)(t + 1);
            #pragma unroll
            for (int j = 0; j < 4; ++j) {
                const unsigned* fp = g_flags + (tid * 4 + j) * 32;
                unsigned v;
                do {
                    asm volatile("ld.acquire.gpu.u32 %0, [%1];"
                                 : "=r"(v) : "l"(fp) : "memory");
                } while (v < target);
            }
        }
        __syncthreads();                    // whole block released

        // ---- stage h_{t+1} (the only post-barrier dependent work) ----
        if (t + 1 < SEQ_LEN) {
            const float* hb = &g_h[(t + 1) & 1][0][0];
            for (int idx = tid; idx < TILE_R * HID / 4; idx += NTHREADS) {
                int r  = idx >> 7;          // 128 quads per row
                int kq = idx & 127;
                float4 v = __ldcv(reinterpret_cast<const float4*>(
                                      hb + (r0 + r) * HID) + kq);
                float2* dst = sV + (IN_DIM + 4 * kq) * SV_PITCH + r;
                dst[0]            = make_float2(v.x, v.x);
                dst[SV_PITCH]     = make_float2(v.y, v.y);
                dst[2 * SV_PITCH] = make_float2(v.z, v.z);
                dst[3 * SV_PITCH] = make_float2(v.w, v.w);
            }
        }
    }

    // ---- final projection p = h_final @ Wph + bp (col-tile-0 blocks) ----
    if (jt == 0) {
        float* sP = reinterpret_cast<float*>(smem);                 // [512][10]
        float* sH = reinterpret_cast<float*>(smem) + HID * NCLS;    // [16][512]

        for (int idx = tid; idx < HID * NCLS; idx += NTHREADS)
            sP[idx] = Wph[idx];
        const float* hf = &g_h[SEQ_LEN & 1][0][0];
        for (int idx = tid; idx < TILE_R * HID; idx += NTHREADS) {
            int r = idx >> 9;
            int k = idx & 511;
            sH[r * HID + k] = __ldcv(hf + (r0 + r) * HID + k);
        }
        __syncthreads();

        for (int idx = tid; idx < TILE_R * NCLS; idx += NTHREADS) {
            int r = idx / NCLS;
            int c = idx - r * NCLS;
            float s = bp[c];
            const float* hr = sH + r * HID;
            #pragma unroll 8
            for (int k = 0; k < HID; ++k)
                s += hr[k] * sP[k * NCLS + c];
            out[(r0 + r) * NCLS + c] = s;
        }
    }
}

extern "C" void kernel_launch(void* const* d_in, const int* in_sizes, int n_in,
                              void* d_out, int out_size)
{
    const float* x   = (const float*)d_in[0];
    const float* Whx = (const float*)d_in[1];
    const float* Whh = (const float*)d_in[2];
    const float* Wph = (const float*)d_in[3];
    const float* bh  = (const float*)d_in[4];
    const float* bp  = (const float*)d_in[5];
    float* out = (float*)d_out;

    // Reset barrier flags every launch (deterministic graph replays).
    void* flags_addr = nullptr;
    cudaGetSymbolAddress(&flags_addr, g_flags);
    cudaMemsetAsync(flags_addr, 0, GRID_DIM * 32 * sizeof(unsigned));

    cudaFuncSetAttribute(rnn_persistent_kernel,
                         cudaFuncAttributeMaxDynamicSharedMemorySize, SMEM_BYTES);

    rnn_persistent_kernel<<<GRID_DIM, NTHREADS, SMEM_BYTES>>>(
        x, Whx, Whh, Wph, bh, bp, out);
}

// round 4
// speedup vs baseline: 1.0014x; 1.0014x over previous
#include <cuda_runtime.h>
#include <cstdint>

// VanillaRNN: p = (scan_t h = tanh(x_t @ Whx + h @ Whh + bh)) @ Wph + bp
// B=256, T=1024, D=64, H=512, C=10, all fp32.
//
// Round 3: persistent kernel, 128 blocks x 512 threads, split-K(4).
//  - Distributed-flag grid barrier (no atomic contention, 1 fence/block).
//  - x_{t+1} staged before the barrier; only h staging is post-barrier.

#define SEQ_LEN   1024
#define IN_DIM    64
#define HID       512
#define NCLS      10
#define BATCH     256
#define KTOT      (IN_DIM + HID)   // 576

#define COL_TILES 8
#define ROW_TILES 16
#define GRID_DIM  (COL_TILES * ROW_TILES)  // 128 blocks, 1 CTA/SM
#define NTHREADS  512
#define KGROUPS   4
#define KCHUNK    (KTOT / KGROUPS)         // 144
#define TILE_C    64
#define TILE_R    16

#define SV_PITCH  18   // float2 per k row (pad: 16B align + bank spread)

// SMEM:
//   sW : [KTOT][TILE_C] float    = 147456 B
//   sV : [KTOT][SV_PITCH] float2 =  82944 B (value duplicated .x/.y)
//        h-region (k>=64) reused as reduction scratch float2[4][512]
//   sB : [TILE_C] float          =    256 B
#define SW_BYTES  (KTOT * TILE_C * 4)
#define SV_BYTES  (KTOT * SV_PITCH * 8)
#define SMEM_BYTES (SW_BYTES + SV_BYTES + TILE_C * 4)   // 230656

__device__ float    g_h[2][BATCH][HID];        // double-buffered hidden state
__device__ unsigned g_flags[GRID_DIM * 32];    // 1 flag / block, 128B stride

__device__ __forceinline__ float2 unpk(unsigned long long v) {
    float2 f;
    asm("mov.b64 {%0, %1}, %2;" : "=f"(f.x), "=f"(f.y) : "l"(v));
    return f;
}
__device__ __forceinline__ void fma2(unsigned long long& d,
                                     unsigned long long a,
                                     unsigned long long b) {
    asm("fma.rn.f32x2 %0, %1, %2, %0;" : "+l"(d) : "l"(a), "l"(b));
}

__global__ void __launch_bounds__(NTHREADS, 1)
rnn_persistent_kernel(const float* __restrict__ x,
                      const float* __restrict__ Whx,
                      const float* __restrict__ Whh,
                      const float* __restrict__ Wph,
                      const float* __restrict__ bh,
                      const float* __restrict__ bp,
                      float* __restrict__ out)
{
    extern __shared__ unsigned char smem[];
    float*  sW   = reinterpret_cast<float*>(smem);               // [KTOT][64]
    float2* sV   = reinterpret_cast<float2*>(smem + SW_BYTES);   // [KTOT][18]
    float2* sRed = sV + IN_DIM * SV_PITCH;                       // in h-region
    float*  sB   = reinterpret_cast<float*>(smem + SW_BYTES + SV_BYTES);

    const int tid = threadIdx.x;
    const int bid = blockIdx.x;
    const int jt  = bid & (COL_TILES - 1);   // col tile
    const int it  = bid >> 3;                // row tile
    const int c0  = jt * TILE_C;
    const int r0  = it * TILE_R;

    // ---- one-time: W slice [Whx; Whh][:, c0:c0+64] + bias ----
    for (int idx = tid; idx < KTOT * TILE_C; idx += NTHREADS) {
        int k = idx / TILE_C;
        int c = idx - k * TILE_C;
        float w = (k < IN_DIM) ? Whx[k * HID + c0 + c]
                               : Whh[(k - IN_DIM) * HID + c0 + c];
        sW[k * TILE_C + c] = w;
    }
    if (tid < TILE_C) sB[tid] = bh[c0 + tid];

    // split-K org: 4 groups x 128 threads; within group 2 rows x 4 cols
    const int kg = tid >> 7;
    const int pg = tid & 127;
    const int r4 = pg & 7;                   // rows 2*r4, 2*r4+1
    const int cq = pg >> 3;                  // cols 4*cq..4*cq+3
    const int k0 = kg * KCHUNK;

    const float*  wp = sW + 4 * cq;
    const float2* vp = sV + 2 * r4;

    // reduction mapping: thread finalizes output pair tid
    const int rcp  = tid & 31;               // colpair 0..31
    const int rrow = tid >> 5;               // row 0..15

    // ---- prologue: h_0 = 0 straight into SMEM; stage x_0 ----
    for (int idx = tid; idx < TILE_R * HID; idx += NTHREADS) {
        int r = idx >> 9;
        int k = idx & 511;
        sV[(IN_DIM + k) * SV_PITCH + r] = make_float2(0.f, 0.f);
    }
    for (int idx = tid; idx < TILE_R * IN_DIM; idx += NTHREADS) {
        int r = idx >> 6;
        int k = idx & 63;
        float v = x[(size_t)(r0 + r) * (SEQ_LEN * IN_DIM) + k];
        sV[k * SV_PITCH + r] = make_float2(v, v);
    }

    for (int t = 0; t < SEQ_LEN; ++t) {
        __syncthreads();   // sV (x_t + h_t) ready

        // ---- partial GEMM over this group's K-chunk ----
        unsigned long long a00 = 0, a01 = 0;
        unsigned long long a10 = 0, a11 = 0;
        #pragma unroll 8
        for (int k = k0; k < k0 + KCHUNK; ++k) {
            longlong2 w = *reinterpret_cast<const longlong2*>(wp + k * TILE_C);
            longlong2 v = *reinterpret_cast<const longlong2*>(vp + k * SV_PITCH);
            fma2(a00, (unsigned long long)v.x, (unsigned long long)w.x);
            fma2(a01, (unsigned long long)v.x, (unsigned long long)w.y);
            fma2(a10, (unsigned long long)v.y, (unsigned long long)w.x);
            fma2(a11, (unsigned long long)v.y, (unsigned long long)w.y);
        }
        __syncthreads();   // all sV reads done; h-region reusable as sRed

        // ---- write partials ----
        {
            float2* rb = sRed + kg * 512;
            rb[(2 * r4)     * 32 + 2 * cq    ] = unpk(a00);
            rb[(2 * r4)     * 32 + 2 * cq + 1] = unpk(a01);
            rb[(2 * r4 + 1) * 32 + 2 * cq    ] = unpk(a10);
            rb[(2 * r4 + 1) * 32 + 2 * cq + 1] = unpk(a11);
        }
        __syncthreads();

        // ---- reduce + bias + tanh + store h_new; stage x_{t+1} ----
        {
            float2 s0 = sRed[tid];
            float2 s1 = sRed[512 + tid];
            float2 s2 = sRed[1024 + tid];
            float2 s3 = sRed[1536 + tid];
            float sx = (s0.x + s1.x) + (s2.x + s3.x) + sB[2 * rcp];
            float sy = (s0.y + s1.y) + (s2.y + s3.y) + sB[2 * rcp + 1];
            float2 o = make_float2(tanhf(sx), tanhf(sy));
            float* hn = &g_h[(t + 1) & 1][0][0];
            *reinterpret_cast<float2*>(hn + (r0 + rrow) * HID + c0 + 2 * rcp) = o;
        }
        if (t + 1 < SEQ_LEN) {
            for (int idx = tid; idx < TILE_R * IN_DIM; idx += NTHREADS) {
                int r = idx >> 6;
                int k = idx & 63;
                float v = x[(size_t)(r0 + r) * (SEQ_LEN * IN_DIM)
                            + (size_t)(t + 1) * IN_DIM + k];
                sV[k * SV_PITCH + r] = make_float2(v, v);
            }
        }

        // ---- distributed-flag grid barrier ----
        __syncthreads();                    // h_new stores issued block-wide
        if (tid == 0) {
            __threadfence();                // make h_new visible gpu-wide
            asm volatile("st.release.gpu.u32 [%0], %1;"
                         :: "l"(g_flags + bid * 32), "r"(t + 1) : "memory");
        }
        if (tid < 32) {
            const unsigned target = (unsigned)(t + 1);
            #pragma unroll
            for (int j = 0; j < 4; ++j) {
                const unsigned* fp = g_flags + (tid * 4 + j) * 32;
                unsigned v;
                do {
                    asm volatile("ld.acquire.gpu.u32 %0, [%1];"
                                 : "=r"(v) : "l"(fp) : "memory");
                } while (v < target);
            }
        }
        __syncthreads();                    // whole block released

        // ---- stage h_{t+1} (the only post-barrier dependent work) ----
        if (t + 1 < SEQ_LEN) {
            const float* hb = &g_h[(t + 1) & 1][0][0];
            for (int idx = tid; idx < TILE_R * HID / 4; idx += NTHREADS) {
                int r  = idx >> 7;          // 128 quads per row
                int kq = idx & 127;
                float4 v = __ldcv(reinterpret_cast<const float4*>(
                                      hb + (r0 + r) * HID) + kq);
                float2* dst = sV + (IN_DIM + 4 * kq) * SV_PITCH + r;
                dst[0]            = make_float2(v.x, v.x);
                dst[SV_PITCH]     = make_float2(v.y, v.y);
                dst[2 * SV_PITCH] = make_float2(v.z, v.z);
                dst[3 * SV_PITCH] = make_float2(v.w, v.w);
            }
        }
    }

    // ---- final projection p = h_final @ Wph + bp (col-tile-0 blocks) ----
    if (jt == 0) {
        float* sP = reinterpret_cast<float*>(smem);                 // [512][10]
        float* sH = reinterpret_cast<float*>(smem) + HID * NCLS;    // [16][512]

        for (int idx = tid; idx < HID * NCLS; idx += NTHREADS)
            sP[idx] = Wph[idx];
        const float* hf = &g_h[SEQ_LEN & 1][0][0];
        for (int idx = tid; idx < TILE_R * HID; idx += NTHREADS) {
            int r = idx >> 9;
            int k = idx & 511;
            sH[r * HID + k] = __ldcv(hf + (r0 + r) * HID + k);
        }
        __syncthreads();

        for (int idx = tid; idx < TILE_R * NCLS; idx += NTHREADS) {
            int r = idx / NCLS;
            int c = idx - r * NCLS;
            float s = bp[c];
            const float* hr = sH + r * HID;
            #pragma unroll 8
            for (int k = 0; k < HID; ++k)
                s += hr[k] * sP[k * NCLS + c];
            out[(r0 + r) * NCLS + c] = s;
        }
    }
}

extern "C" void kernel_launch(void* const* d_in, const int* in_sizes, int n_in,
                              void* d_out, int out_size)
{
    const float* x   = (const float*)d_in[0];
    const float* Whx = (const float*)d_in[1];
    const float* Whh = (const float*)d_in[2];
    const float* Wph = (const float*)d_in[3];
    const float* bh  = (const float*)d_in[4];
    const float* bp  = (const float*)d_in[5];
    float* out = (float*)d_out;

    // Reset barrier flags every launch (deterministic graph replays).
    void* flags_addr = nullptr;
    cudaGetSymbolAddress(&flags_addr, g_flags);
    cudaMemsetAsync(flags_addr, 0, GRID_DIM * 32 * sizeof(unsigned));

    cudaFuncSetAttribute(rnn_persistent_kernel,
                         cudaFuncAttributeMaxDynamicSharedMemorySize, SMEM_BYTES);

    rnn_persistent_kernel<<<GRID_DIM, NTHREADS, SMEM_BYTES>>>(
        x, Whx, Whh, Wph, bh, bp, out);
}

// round 6
// speedup vs baseline: 2.3535x; 2.3502x over previous
#include <cuda_runtime.h>
#include <cuda_bf16.h>
#include <cstdint>

// VanillaRNN via mma.sync (HMMA bf16, fp32 accum), bf16 two-way split for
// near-fp32 accuracy. B=256,T=1024,D=64,H=512,C=10 fp32.
//
// 128 persistent CTAs = 16 row-tiles(16) x 8 col-tiles(64), 256 threads.
// Per step: CTA computes D[16,64] = [x_t|h][16,576] @ W[:,slice], where
// W resident in SMEM (bf16 hi+lo), A staged per step (bf16 hi+lo).
// Warps: 4 K-groups x 2 N-halves; warp = m16 n32 k144, 3 mma products.

#define T_SEQ  1024
#define B_DIM  256
#define D_IN   64
#define H_DIM  512
#define NCLS   10
#define KTOT   576
#define GRID   128
#define NTHR   256
#define TILE_R 16
#define TILE_C 64

#define PKB    1168            // row stride bytes: 576*2 + 16 pad (bank shift)

// SMEM layout (bytes, from dynamic base; base is 16B aligned)
#define OFF_AH   0
#define OFF_AL   (OFF_AH + TILE_R * PKB)          // 18688
#define OFF_BH   (OFF_AL + TILE_R * PKB)          // 37376
#define OFF_BL   (OFF_BH + TILE_C * PKB)          // 112128
#define OFF_RED  (OFF_BL + TILE_C * PKB)          // 186880: 4*16*64 fp32
#define OFF_BIAS (OFF_RED + 16384)                // 203264: 64 fp32
#define SMEM_SZ  (OFF_BIAS + 256 + 16)

__device__ __nv_bfloat16 g_xhi[(size_t)B_DIM * T_SEQ * D_IN];
__device__ __nv_bfloat16 g_xlo[(size_t)B_DIM * T_SEQ * D_IN];
__device__ __nv_bfloat16 g_Hhi[2][B_DIM][H_DIM];
__device__ __nv_bfloat16 g_Hlo[2][B_DIM][H_DIM];
__device__ float         g_hfin[B_DIM][H_DIM];
__device__ unsigned      g_bar;

__device__ __forceinline__ uint32_t smem_u32(const void* p) {
    uint32_t a;
    asm("{ .reg .u64 t; cvta.to.shared.u64 t, %1; cvt.u32.u64 %0, t; }"
        : "=r"(a) : "l"(p));
    return a;
}

#define LDSM4(r0, r1, r2, r3, addr)                                        \
    asm volatile("ldmatrix.sync.aligned.m8n8.x4.shared.b16 "               \
                 "{%0,%1,%2,%3}, [%4];"                                    \
                 : "=r"(r0), "=r"(r1), "=r"(r2), "=r"(r3) : "r"(addr))
#define LDSM2(r0, r1, addr)                                                \
    asm volatile("ldmatrix.sync.aligned.m8n8.x2.shared.b16 "               \
                 "{%0,%1}, [%2];"                                          \
                 : "=r"(r0), "=r"(r1) : "r"(addr))
#define MMA16816(d, a0, a1, a2, a3, b0, b1)                                \
    asm volatile("mma.sync.aligned.m16n8k16.row.col.f32.bf16.bf16.f32 "    \
                 "{%0,%1,%2,%3}, {%4,%5,%6,%7}, {%8,%9}, {%0,%1,%2,%3};"   \
                 : "+f"(d[0]), "+f"(d[1]), "+f"(d[2]), "+f"(d[3])          \
                 : "r"(a0), "r"(a1), "r"(a2), "r"(a3), "r"(b0), "r"(b1))

__device__ __forceinline__ void grid_barrier(int tid, unsigned epoch) {
    __threadfence();
    __syncthreads();
    if (tid == 0) {
        atomicAdd(&g_bar, 1u);
        while (*(volatile unsigned*)&g_bar < epoch * GRID) { }
        __threadfence();
    }
    __syncthreads();
}

__global__ void __launch_bounds__(NTHR, 1)
rnn_hmma_kernel(const float* __restrict__ x,
                const float* __restrict__ Whx,
                const float* __restrict__ Whh,
                const float* __restrict__ Wph,
                const float* __restrict__ bh,
                const float* __restrict__ bp,
                float* __restrict__ out)
{
    extern __shared__ __align__(16) char smg[];
    const uint32_t sb = smem_u32(smg);

    const int tid  = threadIdx.x;
    const int wid  = tid >> 5;
    const int lane = tid & 31;
    const int bid  = blockIdx.x;
    const int jt   = bid & 7;            // col tile
    const int it   = bid >> 3;           // row tile
    const int c0   = jt * TILE_C;
    const int r0   = it * TILE_R;

    float* sBias = reinterpret_cast<float*>(smg + OFF_BIAS);
    float* sRed  = reinterpret_cast<float*>(smg + OFF_RED);

    // ---- one-time: W slice -> SMEM bf16 hi/lo, padded rows [n][k] ----
    for (int i = tid; i < TILE_C * KTOT; i += NTHR) {
        const int n = i / KTOT, k = i - n * KTOT;
        const float w = (k < D_IN) ? Whx[k * H_DIM + c0 + n]
                                   : Whh[(k - D_IN) * H_DIM + c0 + n];
        const __nv_bfloat16 h16 = __float2bfloat16(w);
        const __nv_bfloat16 l16 = __float2bfloat16(w - __bfloat162float(h16));
        *reinterpret_cast<__nv_bfloat16*>(smg + OFF_BH + n * PKB + k * 2) = h16;
        *reinterpret_cast<__nv_bfloat16*>(smg + OFF_BL + n * PKB + k * 2) = l16;
    }
    if (tid < TILE_C) sBias[tid] = bh[c0 + tid];

    // ---- prologue: split all of x into bf16 hi/lo (grid-strided) ----
    {
        const size_t total = (size_t)B_DIM * T_SEQ * D_IN / 4;
        for (size_t i = (size_t)bid * NTHR + tid; i < total;
             i += (size_t)GRID * NTHR) {
            const float4 v = __ldg(reinterpret_cast<const float4*>(x) + i);
            const __nv_bfloat162 hA = __floats2bfloat162_rn(v.x, v.y);
            const __nv_bfloat162 hB = __floats2bfloat162_rn(v.z, v.w);
            const __nv_bfloat162 lA = __floats2bfloat162_rn(
                v.x - __bfloat162float(hA.x), v.y - __bfloat162float(hA.y));
            const __nv_bfloat162 lB = __floats2bfloat162_rn(
                v.z - __bfloat162float(hB.x), v.w - __bfloat162float(hB.y));
            reinterpret_cast<__nv_bfloat162*>(g_xhi)[2 * i]     = hA;
            reinterpret_cast<__nv_bfloat162*>(g_xhi)[2 * i + 1] = hB;
            reinterpret_cast<__nv_bfloat162*>(g_xlo)[2 * i]     = lA;
            reinterpret_cast<__nv_bfloat162*>(g_xlo)[2 * i + 1] = lB;
        }
    }
    grid_barrier(tid, 1);

    // warp roles: kg = K-group (0..3, k base kg*144), nh = N-half (0/1)
    const int kg = wid >> 1;
    const int nh = wid & 1;
    const int kbase = kg * 144;

    // ldmatrix lane address offsets (byte offsets within A / B tiles)
    const uint32_t aoff = (uint32_t)(lane & 15) * PKB
                        + (uint32_t)((lane >> 4) << 4)       // k-block*8 elems
                        + (uint32_t)kbase * 2;
    uint32_t boff[4];
    #pragma unroll
    for (int nf = 0; nf < 4; ++nf)
        boff[nf] = (uint32_t)(nh * 32 + nf * 8 + (lane & 7)) * PKB
                 + (uint32_t)(((lane >> 3) & 1) << 4)
                 + (uint32_t)kbase * 2;

    const uint32_t sAh = sb + OFF_AH, sAl = sb + OFF_AL;
    const uint32_t sBh = sb + OFF_BH, sBl = sb + OFF_BL;

    // epilogue mapping: thread -> 4 consecutive outputs
    const int erow = (tid * 4) >> 6;          // 0..15
    const int ecol = (tid * 4) & 63;          // multiple of 4

    for (int t = 0; t < T_SEQ; ++t) {
        // ---- stage A = [x_t | h_t] bf16 hi/lo into SMEM ----
        for (int u = tid; u < 2 * TILE_R * 72; u += NTHR) {
            const int half = u >= TILE_R * 72;
            const int uu = half ? u - TILE_R * 72 : u;
            const int r = uu / 72;
            const int q = uu - r * 72;         // 16B unit within row
            uint4 v;
            if (q < 8) {
                const __nv_bfloat16* src = (half ? g_xlo : g_xhi)
                    + ((size_t)(r0 + r) * T_SEQ + t) * D_IN + q * 8;
                v = __ldg(reinterpret_cast<const uint4*>(src));
            } else {
                const __nv_bfloat16* src =
                    (half ? &g_Hlo[t & 1][0][0] : &g_Hhi[t & 1][0][0])
                    + (size_t)(r0 + r) * H_DIM + (q - 8) * 8;
                v = __ldcv(reinterpret_cast<const uint4*>(src));
            }
            *reinterpret_cast<uint4*>(smg + (half ? OFF_AL : OFF_AH)
                                      + r * PKB + q * 16) = v;
        }
        __syncthreads();

        // ---- warp GEMM: m16 x n32 x k144, 3-product bf16 split ----
        float acc[4][4] = {};
        #pragma unroll
        for (int s = 0; s < 9; ++s) {
            const uint32_t ka = (uint32_t)s * 32;
            uint32_t ah0, ah1, ah2, ah3, al0, al1, al2, al3;
            LDSM4(ah0, ah1, ah2, ah3, sAh + aoff + ka);
            LDSM4(al0, al1, al2, al3, sAl + aoff + ka);
            #pragma unroll
            for (int nf = 0; nf < 4; ++nf) {
                uint32_t bh0, bh1, bl0, bl1;
                LDSM2(bh0, bh1, sBh + boff[nf] + ka);
                LDSM2(bl0, bl1, sBl + boff[nf] + ka);
                MMA16816(acc[nf], ah0, ah1, ah2, ah3, bh0, bh1);
                MMA16816(acc[nf], al0, al1, al2, al3, bh0, bh1);
                MMA16816(acc[nf], ah0, ah1, ah2, ah3, bl0, bl1);
            }
        }
        __syncthreads();     // A reads done (not strictly needed, cheap)

        // ---- write split-K partials: sRed[kg][16][64] ----
        {
            float* rb = sRed + kg * 1024;
            const int gr0 = lane >> 2;
            const int cc  = nh * 32 + (lane & 3) * 2;
            #pragma unroll
            for (int nf = 0; nf < 4; ++nf) {
                const int c = cc + nf * 8;
                *reinterpret_cast<float2*>(rb + gr0 * 64 + c) =
                    make_float2(acc[nf][0], acc[nf][1]);
                *reinterpret_cast<float2*>(rb + (gr0 + 8) * 64 + c) =
                    make_float2(acc[nf][2], acc[nf][3]);
            }
        }
        __syncthreads();

        // ---- reduce 4 partials + bias + tanh -> h (bf16 hi/lo) ----
        {
            const int base = tid * 4;
            float4 p0 = *reinterpret_cast<float4*>(sRed + base);
            float4 p1 = *reinterpret_cast<float4*>(sRed + 1024 + base);
            float4 p2 = *reinterpret_cast<float4*>(sRed + 2048 + base);
            float4 p3 = *reinterpret_cast<float4*>(sRed + 3072 + base);
            float v[4];
            v[0] = tanhf((p0.x + p1.x) + (p2.x + p3.x) + sBias[ecol]);
            v[1] = tanhf((p0.y + p1.y) + (p2.y + p3.y) + sBias[ecol + 1]);
            v[2] = tanhf((p0.z + p1.z) + (p2.z + p3.z) + sBias[ecol + 2]);
            v[3] = tanhf((p0.w + p1.w) + (p2.w + p3.w) + sBias[ecol + 3]);

            __nv_bfloat162 h01 = __floats2bfloat162_rn(v[0], v[1]);
            __nv_bfloat162 h23 = __floats2bfloat162_rn(v[2], v[3]);
            __nv_bfloat162 l01 = __floats2bfloat162_rn(
                v[0] - __bfloat162float(h01.x), v[1] - __bfloat162float(h01.y));
            __nv_bfloat162 l23 = __floats2bfloat162_rn(
                v[2] - __bfloat162float(h23.x), v[3] - __bfloat162float(h23.y));

            const int row = r0 + erow, col = c0 + ecol;
            *reinterpret_cast<uint2*>(&g_Hhi[(t + 1) & 1][row][col]) =
                make_uint2(*reinterpret_cast<uint32_t*>(&h01),
                           *reinterpret_cast<uint32_t*>(&h23));
            *reinterpret_cast<uint2*>(&g_Hlo[(t + 1) & 1][row][col]) =
                make_uint2(*reinterpret_cast<uint32_t*>(&l01),
                           *reinterpret_cast<uint32_t*>(&l23));
            if (t == T_SEQ - 1)
                *reinterpret_cast<float4*>(&g_hfin[row][col]) =
                    make_float4(v[0], v[1], v[2], v[3]);
        }

        grid_barrier(tid, (unsigned)(t + 2));
    }

    // ---- final projection p = h_final @ Wph + bp (col-tile-0 CTAs) ----
    if (jt == 0) {
        float* sW = reinterpret_cast<float*>(smg + OFF_BH);   // 5120 floats
        float* sH = reinterpret_cast<float*>(smg + OFF_AH);   // 16x512 floats
        for (int i = tid; i < H_DIM * NCLS; i += NTHR)
            sW[i] = Wph[i];
        for (int i = tid; i < TILE_R * H_DIM; i += NTHR) {
            const int r = i >> 9, k = i & 511;
            sH[r * H_DIM + k] = __ldcv(&g_hfin[r0 + r][k]);
        }
        __syncthreads();
        for (int i = tid; i < TILE_R * NCLS; i += NTHR) {
            const int r = i / NCLS, cc = i - (i / NCLS) * NCLS;
            float s = bp[cc];
            const float* hr = sH + r * H_DIM;
            #pragma unroll 8
            for (int k = 0; k < H_DIM; ++k)
                s += hr[k] * sW[k * NCLS + cc];
            out[(r0 + r) * NCLS + cc] = s;
        }
    }
}

extern "C" void kernel_launch(void* const* d_in, const int* in_sizes, int n_in,
                              void* d_out, int out_size)
{
    const float* x   = (const float*)d_in[0];
    const float* Whx = (const float*)d_in[1];
    const float* Whh = (const float*)d_in[2];
    const float* Wph = (const float*)d_in[3];
    const float* bh  = (const float*)d_in[4];
    const float* bp  = (const float*)d_in[5];
    float* out = (float*)d_out;

    // Deterministic per-launch state: barrier counter + zero h_0 (buffer 0).
    void *bar_a = nullptr, *hhi_a = nullptr, *hlo_a = nullptr;
    cudaGetSymbolAddress(&bar_a, g_bar);
    cudaGetSymbolAddress(&hhi_a, g_Hhi);
    cudaGetSymbolAddress(&hlo_a, g_Hlo);
    cudaMemsetAsync(bar_a, 0, sizeof(unsigned));
    cudaMemsetAsync(hhi_a, 0, (size_t)B_DIM * H_DIM * sizeof(__nv_bfloat16));
    cudaMemsetAsync(hlo_a, 0, (size_t)B_DIM * H_DIM * sizeof(__nv_bfloat16));

    cudaFuncSetAttribute(rnn_hmma_kernel,
                         cudaFuncAttributeMaxDynamicSharedMemorySize, SMEM_SZ);

    rnn_hmma_kernel<<<GRID, NTHR, SMEM_SZ>>>(x, Whx, Whh, Wph, bh, bp, out);
}